// round 13
// baseline (speedup 1.0000x reference)
#include <cuda_runtime.h>
#include <cuda_bf16.h>
#include <math.h>

typedef unsigned long long ull;

#define TSTEPS 512
#define BATCH  64
#define FDIM   256
#define HDIM   1024
#define CDIM   257
#define NCTA   128

// lstm_rec smem layout (bytes)
#define OFF_WHI  0          // W hi: 32 rows x 160 16B-units (80KB), XOR-swizzled
#define OFF_WLO  81920      // W lo (80KB)
#define OFF_A0   163840     // act buf 0: hi 16KB + lo 16KB
#define OFF_A1   196608     // act buf 1
#define OFF_MB   229376     // 2 mbarriers
#define OFF_BIAS 229392     // 32 floats
#define SMEM_REC 229520
#define WPITCH   2560       // W row pitch bytes (1280 k x 2B)

// out_mma smem layout (bytes)
#define OW_HI    0          // FW hi: 32 rows x 128 units (64KB)
#define OW_LO    65536
#define OA0      131072
#define OA1      163840
#define OMB      196608
#define ODX      196640     // 32 x 66 floats
#define SMEM_OUT 205088
#define OW_PITCH 2048
#define TLOOP    8

// ---------------- global scratch ----------------
__device__ __align__(128) unsigned char g_xh[(size_t)TSTEPS * 2 * 16384];
__device__ __align__(128) unsigned char g_xl[(size_t)TSTEPS * 2 * 16384];
__device__ __align__(128) unsigned char g_hh[(size_t)TSTEPS * 8 * 16384];
__device__ __align__(128) unsigned char g_hl[(size_t)TSTEPS * 8 * 16384];
__device__ unsigned g_cnt[8];
__device__ unsigned g_root;
__device__ volatile unsigned g_release;

// ---------------- helpers ----------------
static __device__ __forceinline__ float sigmoid_f(float x) {
    return 1.f / (1.f + __expf(-x));
}
static __device__ __forceinline__ float tanh_f(float x) {
    float e = __expf(2.f * x);
    return 1.f - 2.f / (e + 1.f);
}
static __device__ __forceinline__ unsigned smem_u32(const void* p) {
    return (unsigned)__cvta_generic_to_shared(p);
}
static __device__ __forceinline__ void mbar_init(unsigned a) {
    asm volatile("mbarrier.init.shared.b64 [%0], 1;" :: "r"(a) : "memory");
}
static __device__ __forceinline__ void expect_tx(unsigned mbar, unsigned bytes) {
    asm volatile("mbarrier.arrive.expect_tx.shared.b64 _, [%0], %1;"
                 :: "r"(mbar), "r"(bytes) : "memory");
}
static __device__ __forceinline__ void bulk_cp(unsigned dst, const void* src,
                                               unsigned bytes, unsigned mbar) {
    asm volatile("cp.async.bulk.shared::cluster.global.mbarrier::complete_tx::bytes "
                 "[%0], [%1], %2, [%3];"
                 :: "r"(dst), "l"(src), "r"(bytes), "r"(mbar) : "memory");
}
static __device__ __forceinline__ void mbar_wait(unsigned mbar, unsigned phase) {
    asm volatile(
        "{\n\t.reg .pred P;\n\t"
        "LW_%=:\n\t"
        "mbarrier.try_wait.parity.acquire.cta.shared::cta.b64 P, [%0], %1, 0x989680;\n\t"
        "@P bra LD_%=;\n\t"
        "bra LW_%=;\n\t"
        "LD_%=:\n\t}"
        :: "r"(mbar), "r"(phase) : "memory");
}
static __device__ __forceinline__ void ldsm4(unsigned* r, unsigned addr) {
    asm volatile("ldmatrix.sync.aligned.m8n8.x4.shared.b16 {%0,%1,%2,%3}, [%4];"
                 : "=r"(r[0]), "=r"(r[1]), "=r"(r[2]), "=r"(r[3]) : "r"(addr));
}
static __device__ __forceinline__ void ldsm4t(unsigned* r, unsigned addr) {
    asm volatile("ldmatrix.sync.aligned.m8n8.x4.trans.shared.b16 {%0,%1,%2,%3}, [%4];"
                 : "=r"(r[0]), "=r"(r[1]), "=r"(r[2]), "=r"(r[3]) : "r"(addr));
}
static __device__ __forceinline__ void mma16816(float* c, const unsigned* a,
                                                unsigned b0, unsigned b1) {
    asm volatile(
        "mma.sync.aligned.m16n8k16.row.col.f32.bf16.bf16.f32 "
        "{%0,%1,%2,%3},{%4,%5,%6,%7},{%8,%9},{%0,%1,%2,%3};"
        : "+f"(c[0]), "+f"(c[1]), "+f"(c[2]), "+f"(c[3])
        : "r"(a[0]), "r"(a[1]), "r"(a[2]), "r"(a[3]), "r"(b0), "r"(b1));
}
static __device__ __forceinline__ void split_bf(float v, unsigned short& hi_us,
                                                unsigned short& lo_us) {
    __nv_bfloat16 h = __float2bfloat16(v);
    float hf = __bfloat162float(h);
    __nv_bfloat16 l = __float2bfloat16(v - hf);
    unsigned short hu, lu;
    memcpy(&hu, &h, 2); memcpy(&lu, &l, 2);
    hi_us = hu; lo_us = lu;
}

// ===========================================================================
// Kernel 0: x[t][b][f] fp32 -> swizzled bf16 hi/lo act tiles [t][2ch][128k x 64b]
// ===========================================================================
__global__ __launch_bounds__(256) void xsplit(const float* __restrict__ x)
{
    __shared__ float sx[64][129];
    const int t = blockIdx.x;
    for (int half = 0; half < 2; half++) {
        for (int i = threadIdx.x; i < 64 * 128; i += 256) {
            int b = i >> 7, f = i & 127;
            sx[b][f] = x[((size_t)t * BATCH + b) * FDIM + half * 128 + f];
        }
        __syncthreads();
        if (threadIdx.x < 128) {
            int f = threadIdx.x;
            size_t base = ((size_t)t * 2 + half) * 16384 + (size_t)f * 128;
            for (int b8 = 0; b8 < 8; b8++) {
                unsigned short hu[8], lu[8];
#pragma unroll
                for (int e = 0; e < 8; e++)
                    split_bf(sx[b8 * 8 + e][f], hu[e], lu[e]);
                uint4 hv, lv;
                hv.x = ((unsigned)hu[1] << 16) | hu[0];
                hv.y = ((unsigned)hu[3] << 16) | hu[2];
                hv.z = ((unsigned)hu[5] << 16) | hu[4];
                hv.w = ((unsigned)hu[7] << 16) | hu[6];
                lv.x = ((unsigned)lu[1] << 16) | lu[0];
                lv.y = ((unsigned)lu[3] << 16) | lu[2];
                lv.z = ((unsigned)lu[5] << 16) | lu[4];
                lv.w = ((unsigned)lu[7] << 16) | lu[6];
                unsigned us = (unsigned)(b8 ^ (f & 7));
                *(uint4*)(g_xh + base + us * 16) = hv;
                *(uint4*)(g_xl + base + us * 16) = lv;
            }
        }
        __syncthreads();
    }
}

// ===========================================================================
// Kernel 1: persistent mma.sync (bf16x3) recurrence, 512 threads.
// 16 warps = (kh: k-half, jt: j16 tile, bt: b16 tile). Each warp covers
// 4 of 8 k-steps per chunk; cross-kh reduction via two Dx buffers summed
// in the epilogue. 4 warps/SMSP to saturate the HMMA pipe.
// ===========================================================================
__global__ __launch_bounds__(512, 1) void lstm_rec(
    const float* __restrict__ wfh, const float* __restrict__ wih,
    const float* __restrict__ woh, const float* __restrict__ wch,
    const float* __restrict__ wfx, const float* __restrict__ wix,
    const float* __restrict__ wox, const float* __restrict__ wcx,
    const float* __restrict__ bf,  const float* __restrict__ bi,
    const float* __restrict__ bo,  const float* __restrict__ bcv)
{
    extern __shared__ unsigned char sm[];
    const unsigned s0 = smem_u32(sm);
    const unsigned sA = s0 + OFF_A0;
    const unsigned mbd0 = s0 + OFF_MB, mbd1 = s0 + OFF_MB + 8;
    float* biasSm = (float*)(sm + OFF_BIAS);
    float* Dx0 = (float*)(sm + OFF_A0);          // overlay on act buf 0
    float* Dx1 = Dx0 + 32 * 66;

    const int tid = threadIdx.x;
    const int j0 = blockIdx.x * 8;
    const float* WH[4] = {wfh, wih, woh, wch};
    const float* WX[4] = {wfx, wix, wox, wcx};
    const float* BS[4] = {bf, bi, bo, bcv};

    if (tid == 0) {
        mbar_init(mbd0); mbar_init(mbd1);
        asm volatile("fence.proxy.async.shared::cta;" ::: "memory");
    }
    if (tid < 32) biasSm[tid] = BS[tid >> 3][j0 + (tid & 7)];

    // ---- weights: 32 rows (g*8+jl) x 1280 k, bf16 hi/lo, unit-swizzled ----
    for (int it = tid; it < 32 * 160; it += 512) {
        int n = it / 160, u = it % 160, k = u * 8;
        int g = n >> 3, jl = n & 7;
        const float* src = (k < 256)
            ? (WX[g] + (size_t)(j0 + jl) * FDIM + k)
            : (WH[g] + (size_t)(j0 + jl) * HDIM + (k - 256));
        float4 v0 = *(const float4*)src;
        float4 v1 = *(const float4*)(src + 4);
        float f[8] = {v0.x, v0.y, v0.z, v0.w, v1.x, v1.y, v1.z, v1.w};
        unsigned short hu[8], lu[8];
#pragma unroll
        for (int e = 0; e < 8; e++) split_bf(f[e], hu[e], lu[e]);
        uint4 hv, lv;
        hv.x = ((unsigned)hu[1] << 16) | hu[0]; hv.y = ((unsigned)hu[3] << 16) | hu[2];
        hv.z = ((unsigned)hu[5] << 16) | hu[4]; hv.w = ((unsigned)hu[7] << 16) | hu[6];
        lv.x = ((unsigned)lu[1] << 16) | lu[0]; lv.y = ((unsigned)lu[3] << 16) | lu[2];
        lv.z = ((unsigned)lu[5] << 16) | lu[4]; lv.w = ((unsigned)lu[7] << 16) | lu[6];
        unsigned off = (unsigned)n * WPITCH + (unsigned)(u ^ (n & 7)) * 16;
        *(uint4*)(sm + OFF_WHI + off) = hv;
        *(uint4*)(sm + OFF_WLO + off) = lv;
    }
    __syncthreads();

    // ---- per-lane fragment addressing constants ----
    const int l = tid & 31, wid = tid >> 5;
    const int kh = wid >> 3, jt = (wid >> 2) & 1, bt = wid & 3;
    const int mi = l >> 3, r = l & 7;
    const int jloc = jt * 16 + (mi & 1) * 8 + r;
    const unsigned rowAhi = s0 + OFF_WHI + (unsigned)jloc * WPITCH;
    const unsigned rowAlo = s0 + OFF_WLO + (unsigned)jloc * WPITCH;
    const unsigned kb = (unsigned)(mi >> 1);
    const unsigned colB = ((unsigned)((bt * 2 + (mi >> 1)) ^ r)) << 4;
    const int krB = (mi & 1) * 8 + r;
    float* Dm = kh ? Dx1 : Dx0;

    float cst[8];
#pragma unroll
    for (int jl = 0; jl < 8; jl++) cst[jl] = 0.f;
    unsigned ph0 = 0, ph1 = 0;

    // c = chunk position within step st: 0,1 = x(st); 2..9 = h chunk c-2 of st-1
#define ISSUE_C(st, c) do {                                                    \
    int _c = (c); unsigned _mb = (_c & 1) ? mbd1 : mbd0;                       \
    unsigned _dst = sA + (unsigned)(_c & 1) * 32768;                           \
    const unsigned char *_sh, *_sl;                                            \
    if (_c < 2) { size_t _o = ((size_t)(st) * 2 + _c) * 16384;                 \
                  _sh = g_xh + _o; _sl = g_xl + _o; }                          \
    else        { size_t _o = ((size_t)((st) - 1) * 8 + (_c - 2)) * 16384;     \
                  _sh = g_hh + _o; _sl = g_hl + _o; }                          \
    expect_tx(_mb, 32768);                                                     \
    bulk_cp(_dst, _sh, 16384, _mb);                                            \
    bulk_cp(_dst + 16384, _sl, 16384, _mb);                                    \
} while (0)

    for (int t = 0; t < TSTEPS; t++) {
        float C0h[4] = {0.f, 0.f, 0.f, 0.f};
        float C0l[4] = {0.f, 0.f, 0.f, 0.f};
        float C1h[4] = {0.f, 0.f, 0.f, 0.f};
        float C1l[4] = {0.f, 0.f, 0.f, 0.f};
        const int nch = t ? 10 : 2;

        if (t == 0 && tid == 0) { ISSUE_C(0, 0); ISSUE_C(0, 1); }
#pragma unroll 1
        for (int ch = 0; ch < nch; ch++) {
            if (ch & 1) { mbar_wait(mbd1, ph1); ph1 ^= 1; }
            else        { mbar_wait(mbd0, ph0); ph0 ^= 1; }
            const unsigned aHi = sA + (unsigned)(ch & 1) * 32768;
            const unsigned chb = (unsigned)ch * 16;
#pragma unroll
            for (int ks = 0; ks < 4; ks++) {
                const int ksg = kh * 4 + ks;
                unsigned Ah[4], Al[4], Bh[4], Bl[4];
                unsigned ku = chb + (unsigned)ksg * 2 + kb;
                unsigned offA = (ku ^ (unsigned)r) << 4;
                ldsm4(Ah, rowAhi + offA);
                ldsm4(Al, rowAlo + offA);
                unsigned rowB = aHi + (unsigned)(ksg * 16 + krB) * 128 + colB;
                ldsm4t(Bh, rowB);
                ldsm4t(Bl, rowB + 16384);
                mma16816(C0h, Ah, Bh[0], Bh[1]);
                mma16816(C1h, Ah, Bh[2], Bh[3]);
                mma16816(C0l, Ah, Bl[0], Bl[1]);
                mma16816(C1l, Ah, Bl[2], Bl[3]);
                mma16816(C0l, Al, Bh[0], Bh[1]);
                mma16816(C1l, Al, Bh[2], Bh[3]);
            }
            __syncthreads();
            if (tid == 0 && ch + 2 < nch) ISSUE_C(t, ch + 2);
        }

        // ---- C exchange into per-kh buffer (overlay buf0; copies drained) ----
        {
            const int q = l >> 2, c2 = (l & 3) * 2;
            const int row0 = jt * 16 + q, colb = bt * 16 + c2;
            Dm[row0 * 66 + colb]           = C0h[0] + C0l[0];
            Dm[row0 * 66 + colb + 1]       = C0h[1] + C0l[1];
            Dm[(row0 + 8) * 66 + colb]     = C0h[2] + C0l[2];
            Dm[(row0 + 8) * 66 + colb + 1] = C0h[3] + C0l[3];
            Dm[row0 * 66 + colb + 8]           = C1h[0] + C1l[0];
            Dm[row0 * 66 + colb + 9]           = C1h[1] + C1l[1];
            Dm[(row0 + 8) * 66 + colb + 8]     = C1h[2] + C1l[2];
            Dm[(row0 + 8) * 66 + colb + 9]     = C1h[3] + C1l[3];
        }
        __syncthreads();

        if (tid < 64) {
            const int b = tid;
            float z[4][8];
#pragma unroll
            for (int g = 0; g < 4; g++)
#pragma unroll
                for (int jl = 0; jl < 8; jl++) {
                    int idx = (g * 8 + jl) * 66 + b;
                    z[g][jl] = Dx0[idx] + Dx1[idx] + biasSm[g * 8 + jl];
                }
            float hs[8];
#pragma unroll
            for (int jl = 0; jl < 8; jl++) {
                float ff = sigmoid_f(z[0][jl]);
                float ii = sigmoid_f(z[1][jl]);
                float oo = sigmoid_f(z[2][jl]);
                float aa = z[3][jl];
                cst[jl] = ii * tanh_f(aa) + ff * cst[jl];
                hs[jl] = oo * tanh_f(cst[jl]);
            }
            // write h as bf16 hi/lo swizzled act tile (next step's B operand)
            const int hc = j0 >> 7;
            const int klbase = j0 & 127;
            size_t cb = ((size_t)t * 8 + hc) * 16384;
#pragma unroll
            for (int jl = 0; jl < 8; jl++) {
                unsigned short hu, lu;
                split_bf(hs[jl], hu, lu);
                int kl = klbase + jl;
                unsigned us = (unsigned)((b >> 3) ^ jl);
                size_t off = cb + (size_t)kl * 128 + us * 16 + (b & 7) * 2;
                *(unsigned short*)(g_hh + off) = hu;
                *(unsigned short*)(g_hl + off) = lu;
            }
            __threadfence();
        }

        __syncthreads();   // Dx reads done; pending STS drained
        if (t < TSTEPS - 1) {
            if (tid == 0) {
                // issue next step's x chunks NOW — they fly during barrier poll
                ISSUE_C(t + 1, 0); ISSUE_C(t + 1, 1);
                __threadfence();
                int grp = blockIdx.x >> 4;
                unsigned prev = atomicAdd(&g_cnt[grp], 1u);
                if (prev == (unsigned)(t + 1) * 16 - 1) {
                    unsigned pr = atomicAdd(&g_root, 1u);
                    if (pr == (unsigned)(t + 1) * 8 - 1)
                        g_release = (unsigned)(t + 1);
                }
                while (g_release < (unsigned)(t + 1)) { }
                __threadfence();
            }
            __syncthreads();
        }
    }
#undef ISSUE_C
}

// ===========================================================================
// Kernel 2: out = hs @ fco^T + b on tensor cores (bf16x3). Unchanged (237us).
// ===========================================================================
__global__ __launch_bounds__(256, 1) void out_mma(
    const float* __restrict__ fw, const float* __restrict__ fb,
    float* __restrict__ out)
{
    extern __shared__ unsigned char sm[];
    const unsigned s0 = smem_u32(sm);
    const unsigned sA = s0 + OA0;
    const unsigned mb0 = s0 + OMB, mb1 = s0 + OMB + 8;
    float* Dx = (float*)(sm + ODX);

    const int tid = threadIdx.x;
    const int n0 = blockIdx.x * 32;
    const int t0 = blockIdx.y * TLOOP;

    if (tid == 0) {
        mbar_init(mb0); mbar_init(mb1);
        asm volatile("fence.proxy.async.shared::cta;" ::: "memory");
        size_t o0 = ((size_t)t0 * 8 + 0) * 16384;
        size_t o1 = ((size_t)t0 * 8 + 1) * 16384;
        expect_tx(mb0, 32768);
        bulk_cp(sA,         g_hh + o0, 16384, mb0);
        bulk_cp(sA + 16384, g_hl + o0, 16384, mb0);
        expect_tx(mb1, 32768);
        bulk_cp(sA + 32768, g_hh + o1, 16384, mb1);
        bulk_cp(sA + 49152, g_hl + o1, 16384, mb1);
    }

    for (int it = tid; it < 32 * 128; it += 256) {
        int n = it >> 7, u = it & 127, k = u * 8;
        int row = n0 + n;
        float f[8] = {0.f, 0.f, 0.f, 0.f, 0.f, 0.f, 0.f, 0.f};
        if (row < CDIM) {
            const float* src = fw + (size_t)row * HDIM + k;
            float4 v0 = *(const float4*)src;
            float4 v1 = *(const float4*)(src + 4);
            f[0] = v0.x; f[1] = v0.y; f[2] = v0.z; f[3] = v0.w;
            f[4] = v1.x; f[5] = v1.y; f[6] = v1.z; f[7] = v1.w;
        }
        unsigned short hu[8], lu[8];
#pragma unroll
        for (int e = 0; e < 8; e++) split_bf(f[e], hu[e], lu[e]);
        uint4 hv, lv;
        hv.x = ((unsigned)hu[1] << 16) | hu[0]; hv.y = ((unsigned)hu[3] << 16) | hu[2];
        hv.z = ((unsigned)hu[5] << 16) | hu[4]; hv.w = ((unsigned)hu[7] << 16) | hu[6];
        lv.x = ((unsigned)lu[1] << 16) | lu[0]; lv.y = ((unsigned)lu[3] << 16) | lu[2];
        lv.z = ((unsigned)lu[5] << 16) | lu[4]; lv.w = ((unsigned)lu[7] << 16) | lu[6];
        unsigned off = (unsigned)n * OW_PITCH + (unsigned)(u ^ (n & 7)) * 16;
        *(uint4*)(sm + OW_HI + off) = hv;
        *(uint4*)(sm + OW_LO + off) = lv;
    }
    __syncthreads();

    const int l = tid & 31, wid = tid >> 5;
    const int jt = wid >> 2, bt = wid & 3;
    const int mi = l >> 3, r = l & 7;
    const int nloc = jt * 16 + (mi & 1) * 8 + r;
    const unsigned rowAhi = s0 + OW_HI + (unsigned)nloc * OW_PITCH;
    const unsigned rowAlo = s0 + OW_LO + (unsigned)nloc * OW_PITCH;
    const unsigned kb = (unsigned)(mi >> 1);
    const unsigned colB = ((unsigned)((bt * 2 + (mi >> 1)) ^ r)) << 4;
    const int krB = (mi & 1) * 8 + r;

    unsigned ph0 = 0, ph1 = 0;

#define OISSUE(tt_, c_) do {                                                   \
    int _c = (c_); unsigned _mb = (_c & 1) ? mb1 : mb0;                        \
    unsigned _dst = sA + (unsigned)(_c & 1) * 32768;                           \
    size_t _o = ((size_t)(tt_) * 8 + _c) * 16384;                              \
    expect_tx(_mb, 32768);                                                     \
    bulk_cp(_dst, g_hh + _o, 16384, _mb);                                      \
    bulk_cp(_dst + 16384, g_hl + _o, 16384, _mb);                              \
} while (0)

    for (int tt = 0; tt < TLOOP; tt++) {
        const int t = t0 + tt;
        float C0h[4] = {0.f, 0.f, 0.f, 0.f};
        float C0l[4] = {0.f, 0.f, 0.f, 0.f};
        float C1h[4] = {0.f, 0.f, 0.f, 0.f};
        float C1l[4] = {0.f, 0.f, 0.f, 0.f};
#pragma unroll 1
        for (int ch = 0; ch < 8; ch++) {
            if (ch & 1) { mbar_wait(mb1, ph1); ph1 ^= 1; }
            else        { mbar_wait(mb0, ph0); ph0 ^= 1; }
            const unsigned aHi = sA + (unsigned)(ch & 1) * 32768;
            const unsigned chb = (unsigned)ch * 16;
#pragma unroll
            for (int ks = 0; ks < 8; ks++) {
                unsigned Ah[4], Al[4], Bh[4], Bl[4];
                unsigned ku = chb + (unsigned)ks * 2 + kb;
                unsigned offA = (ku ^ (unsigned)r) << 4;
                ldsm4(Ah, rowAhi + offA);
                ldsm4(Al, rowAlo + offA);
                unsigned rowB = aHi + (unsigned)(ks * 16 + krB) * 128 + colB;
                ldsm4t(Bh, rowB);
                ldsm4t(Bl, rowB + 16384);
                mma16816(C0h, Ah, Bh[0], Bh[1]);
                mma16816(C1h, Ah, Bh[2], Bh[3]);
                mma16816(C0l, Ah, Bl[0], Bl[1]);
                mma16816(C1l, Ah, Bl[2], Bl[3]);
                mma16816(C0l, Al, Bh[0], Bh[1]);
                mma16816(C1l, Al, Bh[2], Bh[3]);
            }
            __syncthreads();
            if (tid == 0) {
                int nxt = ch + 2;
                if (nxt < 8) OISSUE(t, nxt);
                else if (tt + 1 < TLOOP) OISSUE(t + 1, nxt - 8);
            }
        }
        {
            const int q = l >> 2, c2 = (l & 3) * 2;
            const int row0 = jt * 16 + q, colb = bt * 16 + c2;
            Dx[row0 * 66 + colb]           = C0h[0] + C0l[0];
            Dx[row0 * 66 + colb + 1]       = C0h[1] + C0l[1];
            Dx[(row0 + 8) * 66 + colb]     = C0h[2] + C0l[2];
            Dx[(row0 + 8) * 66 + colb + 1] = C0h[3] + C0l[3];
            Dx[row0 * 66 + colb + 8]           = C1h[0] + C1l[0];
            Dx[row0 * 66 + colb + 9]           = C1h[1] + C1l[1];
            Dx[(row0 + 8) * 66 + colb + 8]     = C1h[2] + C1l[2];
            Dx[(row0 + 8) * 66 + colb + 9]     = C1h[3] + C1l[3];
        }
        __syncthreads();
        {
            const int b = tid & 63, nq = tid >> 6;
#pragma unroll
            for (int e = 0; e < 8; e++) {
                int nl = nq * 8 + e, n = n0 + nl;
                if (n < CDIM)
                    out[((size_t)t * BATCH + b) * CDIM + n] =
                        Dx[nl * 66 + b] + fb[n];
            }
        }
    }
#undef OISSUE
}

__global__ void init_k() {
    g_root = 0; g_release = 0;
    for (int i = 0; i < 8; i++) g_cnt[i] = 0;
}

extern "C" void kernel_launch(void* const* d_in, const int* in_sizes, int n_in,
                              void* d_out, int out_size)
{
    const float* x     = (const float*)d_in[0];
    const float* wfx_w = (const float*)d_in[1];
    const float* wfx_b = (const float*)d_in[2];
    const float* wix_w = (const float*)d_in[3];
    const float* wix_b = (const float*)d_in[4];
    const float* wox_w = (const float*)d_in[5];
    const float* wox_b = (const float*)d_in[6];
    const float* wcx_w = (const float*)d_in[7];
    const float* wcx_b = (const float*)d_in[8];
    const float* wfh_w = (const float*)d_in[9];
    const float* wih_w = (const float*)d_in[10];
    const float* woh_w = (const float*)d_in[11];
    const float* wch_w = (const float*)d_in[12];
    const float* fco_w = (const float*)d_in[13];
    const float* fco_b = (const float*)d_in[14];
    float* out = (float*)d_out;

    cudaFuncSetAttribute(lstm_rec, cudaFuncAttributeMaxDynamicSharedMemorySize,
                         SMEM_REC);
    cudaFuncSetAttribute(out_mma, cudaFuncAttributeMaxDynamicSharedMemorySize,
                         SMEM_OUT);

    init_k<<<1, 1>>>();
    xsplit<<<TSTEPS, 256>>>(x);
    lstm_rec<<<NCTA, 512, SMEM_REC>>>(
        wfh_w, wih_w, woh_w, wch_w,
        wfx_w, wix_w, wox_w, wcx_w,
        wfx_b, wix_b, wox_b, wcx_b);
    out_mma<<<dim3(9, TSTEPS / TLOOP), 256, SMEM_OUT>>>(fco_w, fco_b, out);
}